// round 9
// baseline (speedup 1.0000x reference)
#include <cuda_runtime.h>

#define NUM_G 4096
#define D4    32          // 128 floats = 32 float4 per row
#define DHID  128
#define TPB   512
#define RG    16          // row groups in pass 1 (TPB / 32)
#define EPSV  1e-5f

// Warp-cooperative 32-ary lower_bound over sorted batch (values < 4096).
// b32 viewed as int32 words; element i is at word (i << sh) — sh=1 for int64
// input (low word, little-endian), sh=0 for int32. 5 probe rounds for n=1e6.
__device__ __forceinline__ int warp_lower_bound(const int* __restrict__ b32,
                                                int sh, int n, int target, int lane)
{
    int lo = 0, len = n;
    while (len > 32) {
        int chunk = (len + 31) >> 5;
        int pos = lo + lane * chunk;
        bool lt = (pos < lo + len) && (b32[pos << sh] < target);
        int k = __popc(__ballot_sync(0xffffffffu, lt));
        if (k == 0) {
            len = 1;                      // answer is exactly lo
        } else if (k == 32) {
            int nl = lo + 31 * chunk + 1; // answer in (last probe, lo+len]
            len = lo + len - nl;
            lo = nl;
        } else {
            int nl = lo + (k - 1) * chunk + 1;
            int hi = min(lo + k * chunk + 1, lo + len);
            len = hi - nl;
            lo = nl;
        }
    }
    bool lt = (lane < len) && (b32[(lo + lane) << sh] < target);
    return lo + __popc(__ballot_sync(0xffffffffu, lt));
}

__device__ __forceinline__ void acc(float4& s, float4& q, const float4 v)
{
    s.x += v.x; s.y += v.y; s.z += v.z; s.w += v.w;
    q.x += v.x * v.x; q.y += v.y * v.y;
    q.z += v.z * v.z; q.w += v.w * v.w;
}

__global__ __launch_bounds__(TPB, 2) void graphnorm_kernel(
    const float4* __restrict__ x4,
    const int*    __restrict__ b32,
    const float*  __restrict__ weight,
    const float*  __restrict__ bias,
    float4*       __restrict__ out4,
    int n)
{
    __shared__ float4 red_s[RG][D4];
    __shared__ float4 red_q[RG][D4];
    __shared__ float4 sc_s[D4];
    __shared__ float4 sh_s[D4];
    __shared__ int bounds[2];

    const int g    = blockIdx.x;
    const int tid  = threadIdx.x;
    const int c4   = tid & (D4 - 1);   // float4 column
    const int rg   = tid >> 5;         // row group / warp id
    const int lane = tid & 31;

    // ---- Segment boundaries: warp 0 finds lower_bound(g), warp 1
    //      lower_bound(g+1). Runtime dtype detection: int64 (LE) => odd
    //      32-bit words near the end are high words of values < 4096. ----
    if (rg < 2) {
        int probe = b32[n - 1] | b32[n - 3] | b32[n - 5] | b32[n - 7];
        int sh = (probe == 0) ? 1 : 0;
        int res = warp_lower_bound(b32, sh, n, g + rg, lane);
        if (lane == 0) bounds[rg] = res;
    }
    __syncthreads();
    const int start = bounds[0];
    const int end   = bounds[1];
    const int cnt   = end - start;

    // ---- Pass 1: per-column sum / sumsq (unroll x4: 4 independent
    //      LDG.128 per warp in flight) ----
    float4 s = make_float4(0.f, 0.f, 0.f, 0.f);
    float4 q = make_float4(0.f, 0.f, 0.f, 0.f);
    int r = start + rg;
    for (; r + 3 * RG < end; r += 4 * RG) {
        float4 v0 = x4[(r         ) * D4 + c4];
        float4 v1 = x4[(r +     RG) * D4 + c4];
        float4 v2 = x4[(r + 2 * RG) * D4 + c4];
        float4 v3 = x4[(r + 3 * RG) * D4 + c4];
        acc(s, q, v0);
        acc(s, q, v1);
        acc(s, q, v2);
        acc(s, q, v3);
    }
    for (; r < end; r += RG) {
        float4 v = x4[r * D4 + c4];
        acc(s, q, v);
    }
    red_s[rg][c4] = s;
    red_q[rg][c4] = q;
    __syncthreads();

    // ---- Flat parallel reduction + fold into scale/shift.
    //      128 threads, one scalar column each: 16 conflict-free LDS per
    //      sum, fully pipelined. ----
    if (tid < DHID) {
        const float* ps = reinterpret_cast<const float*>(red_s);
        const float* pq = reinterpret_cast<const float*>(red_q);
        float S = 0.f, Q = 0.f;
        #pragma unroll
        for (int k = 0; k < RG; ++k) {
            S += ps[k * DHID + tid];
            Q += pq[k * DHID + tid];
        }
        float w = weight[tid];
        float b = bias[tid];
        float sc, sh;
        if (cnt > 1) {
            float inv_n = 1.0f / (float)cnt;
            float m = S * inv_n;
            float v = Q * inv_n - m * m;
            sc = w * rsqrtf(v + EPSV);
            sh = b - m * sc;
        } else {
            // cnt <= 1: reference leaves mean=0, var=1
            sc = w * rsqrtf(1.0f + EPSV);
            sh = b;
        }
        reinterpret_cast<float*>(sc_s)[tid] = sc;
        reinterpret_cast<float*>(sh_s)[tid] = sh;
    }
    __syncthreads();

    // ---- Pass 2: normalize (unroll x2, hoisted sc/sh). x re-read hits L2;
    //      streaming stores keep the output from evicting x segments. ----
    const float4 sc = sc_s[c4];
    const float4 sh = sh_s[c4];
    const int jend = end * D4;
    int j = start * D4 + tid;
    for (; j + TPB < jend; j += 2 * TPB) {
        float4 v0 = x4[j];
        float4 v1 = x4[j + TPB];
        float4 o0, o1;
        o0.x = v0.x * sc.x + sh.x; o0.y = v0.y * sc.y + sh.y;
        o0.z = v0.z * sc.z + sh.z; o0.w = v0.w * sc.w + sh.w;
        o1.x = v1.x * sc.x + sh.x; o1.y = v1.y * sc.y + sh.y;
        o1.z = v1.z * sc.z + sh.z; o1.w = v1.w * sc.w + sh.w;
        __stcs(&out4[j      ], o0);
        __stcs(&out4[j + TPB], o1);
    }
    if (j < jend) {
        float4 v = x4[j];
        float4 o;
        o.x = v.x * sc.x + sh.x;
        o.y = v.y * sc.y + sh.y;
        o.z = v.z * sc.z + sh.z;
        o.w = v.w * sc.w + sh.w;
        __stcs(&out4[j], o);
    }
}

extern "C" void kernel_launch(void* const* d_in, const int* in_sizes, int n_in,
                              void* d_out, int out_size)
{
    const float* x      = (const float*)d_in[0];
    const int*   batch  = (const int*)d_in[1];   // int32 or int64; detected on device
    const float* weight = (const float*)d_in[2];
    const float* bias   = (const float*)d_in[3];
    float*       out    = (float*)d_out;

    int n = in_sizes[1];  // number of nodes

    graphnorm_kernel<<<NUM_G, TPB>>>(
        reinterpret_cast<const float4*>(x), batch, weight, bias,
        reinterpret_cast<float4*>(out), n);
}